// round 2
// baseline (speedup 1.0000x reference)
#include <cuda_runtime.h>
#include <math.h>
#include <stdint.h>

// ---------------- problem constants ----------------
#define BATCH   4
#define LSEQ    1024
#define DM      512
#define DI      1024      // d_inner
#define DS      16        // d_state
#define DTR     32        // dt_rank
#define NROWS   (BATCH*LSEQ)   // 4096
#define LN_EPS  1e-5f

// ---------------- scratch (device globals; no allocs allowed) ----------------
__device__ float g_xz[NROWS * 2 * DI];   // in_proj output  [4096, 2048]
__device__ float g_xs[NROWS * DI];       // conv+silu       [4096, 1024]
__device__ float g_dbc[NROWS * 64];      // x_proj output   [4096, 64] (dt|B|C)
__device__ float g_delta[NROWS * DI];    // softplus(dt@Wdt+b)
__device__ float g_y[NROWS * DI];        // scan out (gated in scan epilogue)
__device__ float g_res[NROWS * DM];      // out_proj + residual (LN input)

// ---------------- tf32 helpers ----------------
__device__ __forceinline__ uint32_t f2tf32(float x) {
    uint32_t r;
    asm("cvt.rna.tf32.f32 %0, %1;" : "=r"(r) : "f"(x));
    return r;
}

__device__ __forceinline__ void mma_tf32(
    float& d0, float& d1, float& d2, float& d3,
    uint32_t a0, uint32_t a1, uint32_t a2, uint32_t a3,
    uint32_t b0, uint32_t b1)
{
    asm volatile(
        "mma.sync.aligned.m16n8k8.row.col.f32.tf32.tf32.f32 "
        "{%0,%1,%2,%3}, {%4,%5,%6,%7}, {%8,%9}, {%0,%1,%2,%3};\n"
        : "+f"(d0), "+f"(d1), "+f"(d2), "+f"(d3)
        : "r"(a0), "r"(a1), "r"(a2), "r"(a3), "r"(b0), "r"(b1));
}

// ---------------- tensor-core GEMM: C[M,N] = A[M,K] @ B[K,N] ----------------
// Block tile 128x64, BK=32, 256 threads = 8 warps, warp tile 32x32.
// mode 0: store;  mode 1: store + aux (residual rows, ldc);  mode 2: softplus(acc + aux[col])
#define BM 128
#define BN 64
#define BK 32

__global__ __launch_bounds__(256) void mma_gemm(
    const float* __restrict__ A, const float* __restrict__ B,
    float* __restrict__ C, const float* __restrict__ aux,
    int K, int lda, int ldb, int ldc, int mode)
{
    __shared__ uint32_t As[BM][36];   // row-major A tile (tf32 bits), pad to 36
    __shared__ uint32_t Bs[BK][68];   // k-major B tile, pad to 68

    const int tid = threadIdx.x;
    const int bm = blockIdx.y * BM;
    const int bn = blockIdx.x * BN;
    const int w  = tid >> 5;
    const int lane = tid & 31;
    const int g  = lane >> 2;        // groupID 0..7
    const int tg = lane & 3;         // thread-in-group 0..3
    const int wm = (w & 3) * 32;     // warp M offset (4 warps in M)
    const int wn = (w >> 2) * 32;    // warp N offset (2 warps in N)

    // gmem load coords
    const int ra = tid >> 3;            // 0..31, A rows (4 passes of 32)
    const int ca = (tid & 7) * 4;       // A col within BK
    const int rb = tid >> 4;            // 0..15, B rows (2 passes of 16)
    const int cb = (tid & 15) * 4;      // B col within BN

    float acc[2][4][4];
#pragma unroll
    for (int i = 0; i < 2; i++)
#pragma unroll
        for (int j = 0; j < 4; j++)
#pragma unroll
            for (int r = 0; r < 4; r++) acc[i][j][r] = 0.f;

    const int nk = K / BK;

    // prefetch kblock 0
    float4 pa[4], pb[2];
#pragma unroll
    for (int p = 0; p < 4; p++)
        pa[p] = *(const float4*)(A + (size_t)(bm + ra + p * 32) * lda + ca);
#pragma unroll
    for (int p = 0; p < 2; p++)
        pb[p] = *(const float4*)(B + (size_t)(rb + p * 16) * ldb + bn + cb);

    for (int kb = 0; kb < nk; kb++) {
        // commit prefetched tile to smem (tf32-converted)
#pragma unroll
        for (int p = 0; p < 4; p++) {
            uint4 v;
            v.x = f2tf32(pa[p].x); v.y = f2tf32(pa[p].y);
            v.z = f2tf32(pa[p].z); v.w = f2tf32(pa[p].w);
            *(uint4*)&As[ra + p * 32][ca] = v;
        }
#pragma unroll
        for (int p = 0; p < 2; p++) {
            uint4 v;
            v.x = f2tf32(pb[p].x); v.y = f2tf32(pb[p].y);
            v.z = f2tf32(pb[p].z); v.w = f2tf32(pb[p].w);
            *(uint4*)&Bs[rb + p * 16][cb] = v;
        }
        __syncthreads();

        // prefetch next kblock
        if (kb + 1 < nk) {
            int k0 = (kb + 1) * BK;
#pragma unroll
            for (int p = 0; p < 4; p++)
                pa[p] = *(const float4*)(A + (size_t)(bm + ra + p * 32) * lda + k0 + ca);
#pragma unroll
            for (int p = 0; p < 2; p++)
                pb[p] = *(const float4*)(B + (size_t)(k0 + rb + p * 16) * ldb + bn + cb);
        }

        // compute: 4 k-steps of 8
#pragma unroll
        for (int ks = 0; ks < 4; ks++) {
            const int k8 = ks * 8;
            uint32_t af[2][4];
#pragma unroll
            for (int mt = 0; mt < 2; mt++) {
                int r0 = wm + mt * 16 + g;
                af[mt][0] = As[r0][k8 + tg];
                af[mt][1] = As[r0 + 8][k8 + tg];
                af[mt][2] = As[r0][k8 + tg + 4];
                af[mt][3] = As[r0 + 8][k8 + tg + 4];
            }
#pragma unroll
            for (int nt = 0; nt < 4; nt++) {
                int c0 = wn + nt * 8 + g;
                uint32_t b0 = Bs[k8 + tg][c0];
                uint32_t b1 = Bs[k8 + tg + 4][c0];
#pragma unroll
                for (int mt = 0; mt < 2; mt++)
                    mma_tf32(acc[mt][nt][0], acc[mt][nt][1],
                             acc[mt][nt][2], acc[mt][nt][3],
                             af[mt][0], af[mt][1], af[mt][2], af[mt][3],
                             b0, b1);
            }
        }
        __syncthreads();
    }

    // epilogue
#pragma unroll
    for (int mt = 0; mt < 2; mt++) {
#pragma unroll
        for (int nt = 0; nt < 4; nt++) {
            int grow = bm + wm + mt * 16 + g;
            int gcol = bn + wn + nt * 8 + 2 * tg;
            float v0 = acc[mt][nt][0], v1 = acc[mt][nt][1];
            float v2 = acc[mt][nt][2], v3 = acc[mt][nt][3];
            if (mode == 1) {
                float2 r0 = *(const float2*)(aux + (size_t)grow * ldc + gcol);
                float2 r1 = *(const float2*)(aux + (size_t)(grow + 8) * ldc + gcol);
                v0 += r0.x; v1 += r0.y; v2 += r1.x; v3 += r1.y;
            } else if (mode == 2) {
                float b0 = aux[gcol], b1 = aux[gcol + 1];
                v0 += b0; v1 += b1; v2 += b0; v3 += b1;
                v0 = (v0 > 20.f) ? v0 : log1pf(__expf(v0));
                v1 = (v1 > 20.f) ? v1 : log1pf(__expf(v1));
                v2 = (v2 > 20.f) ? v2 : log1pf(__expf(v2));
                v3 = (v3 > 20.f) ? v3 : log1pf(__expf(v3));
            }
            float2 o0 = {v0, v1}, o1 = {v2, v3};
            *(float2*)(C + (size_t)grow * ldc + gcol) = o0;
            *(float2*)(C + (size_t)(grow + 8) * ldc + gcol) = o1;
        }
    }
}

// ---------------- depthwise causal conv (k=4) + bias + silu ----------------
__global__ __launch_bounds__(256) void conv_silu_k(
    const float* __restrict__ cw, const float* __restrict__ cb)
{
    int idx = blockIdx.x * 256 + threadIdx.x;   // over NROWS*DI
    int d = idx & (DI - 1);
    int row = idx >> 10;      // DI = 1024
    int t = row & (LSEQ - 1);
    float acc = cb[d];
#pragma unroll
    for (int k = 0; k < 4; k++) {
        int tt = t - 3 + k;
        if (tt >= 0)
            acc = fmaf(g_xz[(size_t)(row - 3 + k) * (2 * DI) + d], cw[d * 4 + k], acc);
    }
    g_xs[idx] = acc / (1.f + __expf(-acc));
}

// ---------------- selective scan (gate fused) ----------------
// 16 lanes per channel (one state each), 2 channels per warp.
__global__ __launch_bounds__(256) void scan_k(
    const float* __restrict__ A_log, const float* __restrict__ Dsk)
{
    int tid = blockIdx.x * 256 + threadIdx.x;
    int w = tid >> 5;
    int lane = tid & 31;
    int half = lane >> 4;
    int n = lane & 15;
    int b = w / (DI / 2);
    int dp = w % (DI / 2);
    int d = dp * 2 + half;

    float a = -expf(A_log[d * DS + n]);
    float Dv = Dsk[d];

    const float* dptr  = g_delta + (size_t)b * LSEQ * DI + d;
    const float* xptr  = g_xs    + (size_t)b * LSEQ * DI + d;
    const float* bcptr = g_dbc   + (size_t)b * LSEQ * 64;
    const float* zptr  = g_xz    + (size_t)b * LSEQ * 2 * DI + DI + d;
    float*       yptr  = g_y     + (size_t)b * LSEQ * DI + d;

    float h = 0.f;
    for (int t = 0; t < LSEQ; t++) {
        float delta = __ldg(dptr);  dptr += DI;
        float xs    = __ldg(xptr);  xptr += DI;
        float Bn = __ldg(bcptr + 32 + n);
        float Cn = __ldg(bcptr + 48 + n);
        bcptr += 64;
        float dA = __expf(delta * a);
        h = fmaf(dA, h, (delta * xs) * Bn);
        float p = h * Cn;
        p += __shfl_xor_sync(0xffffffffu, p, 8);
        p += __shfl_xor_sync(0xffffffffu, p, 4);
        p += __shfl_xor_sync(0xffffffffu, p, 2);
        p += __shfl_xor_sync(0xffffffffu, p, 1);
        if (n == 0) {
            float z = __ldg(zptr);
            float y = fmaf(xs, Dv, p);
            *yptr = y * (z / (1.f + __expf(-z)));
        }
        zptr += 2 * DI;
        yptr += DI;
    }
}

// ---------------- layernorm over DM=512 ----------------
__global__ __launch_bounds__(256) void ln_k(
    const float* __restrict__ g, const float* __restrict__ bb,
    float* __restrict__ out)
{
    __shared__ float red[256];
    int row = blockIdx.x;
    const float* r = g_res + (size_t)row * DM;
    int tid = threadIdx.x;
    float v0 = r[tid], v1 = r[tid + 256];
    red[tid] = v0 + v1;
    __syncthreads();
    for (int o = 128; o > 0; o >>= 1) {
        if (tid < o) red[tid] += red[tid + o];
        __syncthreads();
    }
    float mean = red[0] * (1.f / 512.f);
    __syncthreads();
    float d0 = v0 - mean, d1 = v1 - mean;
    red[tid] = d0 * d0 + d1 * d1;
    __syncthreads();
    for (int o = 128; o > 0; o >>= 1) {
        if (tid < o) red[tid] += red[tid + o];
        __syncthreads();
    }
    float rs = rsqrtf(red[0] * (1.f / 512.f) + LN_EPS);
    out[(size_t)row * DM + tid]       = d0 * rs * g[tid]       + bb[tid];
    out[(size_t)row * DM + tid + 256] = d1 * rs * g[tid + 256] + bb[tid + 256];
}

// ---------------- host orchestration ----------------
extern "C" void kernel_launch(void* const* d_in, const int* in_sizes, int n_in,
                              void* d_out, int out_size)
{
    const float* x     = (const float*)d_in[0];   // [4,1024,512]
    const float* Wi    = (const float*)d_in[1];   // [2,512,2048]
    const float* cw    = (const float*)d_in[2];   // [2,1024,1,4]
    const float* cb    = (const float*)d_in[3];   // [2,1024]
    const float* Wx    = (const float*)d_in[4];   // [2,1024,64]
    const float* Wdt   = (const float*)d_in[5];   // [2,32,1024]
    const float* bdt   = (const float*)d_in[6];   // [2,1024]
    const float* A_log = (const float*)d_in[7];   // [2,1024,16]
    const float* Dsk   = (const float*)d_in[8];   // [2,1024]
    const float* Wo    = (const float*)d_in[9];   // [2,1024,512]
    const float* lng   = (const float*)d_in[10];  // [2,512]
    const float* lnb   = (const float*)d_in[11];  // [2,512]
    float* out = (float*)d_out;

    float *p_xz, *p_xs, *p_dbc, *p_delta, *p_y, *p_res;
    cudaGetSymbolAddress((void**)&p_xz, g_xz);
    cudaGetSymbolAddress((void**)&p_xs, g_xs);
    cudaGetSymbolAddress((void**)&p_dbc, g_dbc);
    cudaGetSymbolAddress((void**)&p_delta, g_delta);
    cudaGetSymbolAddress((void**)&p_y, g_y);
    cudaGetSymbolAddress((void**)&p_res, g_res);

    const int EW_BLOCKS = (NROWS * DI) / 256;   // 16384

    for (int l = 0; l < 2; l++) {
        const float* hin = (l == 0) ? x : out;

        // GEMM1: xz = hin @ Wi[l]   [4096,512]x[512,2048]
        mma_gemm<<<dim3(2 * DI / BN, NROWS / BM), 256>>>(
            hin, Wi + (size_t)l * DM * 2 * DI, p_xz, nullptr,
            DM, DM, 2 * DI, 2 * DI, 0);

        // conv + silu
        conv_silu_k<<<EW_BLOCKS, 256>>>(cw + (size_t)l * DI * 4, cb + (size_t)l * DI);

        // GEMM2: dbc = xs @ Wx[l]   [4096,1024]x[1024,64]
        mma_gemm<<<dim3(64 / BN, NROWS / BM), 256>>>(
            p_xs, Wx + (size_t)l * DI * 64, p_dbc, nullptr,
            DI, DI, 64, 64, 0);

        // GEMM3: delta = softplus(dt @ Wdt[l] + bdt)   [4096,32]x[32,1024]
        mma_gemm<<<dim3(DI / BN, NROWS / BM), 256>>>(
            p_dbc, Wdt + (size_t)l * DTR * DI, p_delta, bdt + (size_t)l * DI,
            DTR, 64, DI, DI, 2);

        // selective scan (+D skip, +gate fused)
        scan_k<<<(BATCH * (DI / 2) * 32) / 256, 256>>>(
            A_log + (size_t)l * DI * DS, Dsk + (size_t)l * DI);

        // GEMM4: res = y @ Wo[l] + hin   [4096,1024]x[1024,512]
        mma_gemm<<<dim3(DM / BN, NROWS / BM), 256>>>(
            p_y, Wo + (size_t)l * DI * DM, p_res, hin,
            DI, DI, DM, DM, 1);

        // layernorm -> out
        ln_k<<<NROWS, 256>>>(lng + (size_t)l * DM, lnb + (size_t)l * DM, out);
    }
}

// round 3
// speedup vs baseline: 2.2113x; 2.2113x over previous
#include <cuda_runtime.h>
#include <math.h>
#include <stdint.h>

// ---------------- problem constants ----------------
#define BATCH   4
#define LSEQ    1024
#define DM      512
#define DI      1024      // d_inner
#define DS      16        // d_state
#define DTR     32        // dt_rank
#define NROWS   (BATCH*LSEQ)   // 4096
#define LN_EPS  1e-5f

// ---------------- scratch (device globals; no allocs allowed) ----------------
__device__ float g_xinT[BATCH * DI * LSEQ];   // in_proj x-half, [b][d][t]
__device__ float g_zT  [BATCH * DI * LSEQ];   // in_proj z-half, [b][d][t]
__device__ float g_xsT [BATCH * DI * LSEQ];   // conv+silu, [b][d][t] (scan)
__device__ float g_xs  [NROWS * DI];          // conv+silu, [row][d]  (GEMM2)
__device__ float g_dbc [NROWS * 64];          // x_proj out [row][64] (dt|B|C)
__device__ float g_dT  [BATCH * DI * LSEQ];   // delta, [b][d][t]
__device__ float g_y   [NROWS * DI];          // scan out (gated), [row][d]
__device__ float g_res [NROWS * DM];          // out_proj + residual (LN input)

// ---------------- tf32 helpers ----------------
__device__ __forceinline__ uint32_t f2tf32(float x) {
    uint32_t r;
    asm("cvt.rna.tf32.f32 %0, %1;" : "=r"(r) : "f"(x));
    return r;
}

__device__ __forceinline__ void mma_tf32(
    float& d0, float& d1, float& d2, float& d3,
    uint32_t a0, uint32_t a1, uint32_t a2, uint32_t a3,
    uint32_t b0, uint32_t b1)
{
    asm volatile(
        "mma.sync.aligned.m16n8k8.row.col.f32.tf32.tf32.f32 "
        "{%0,%1,%2,%3}, {%4,%5,%6,%7}, {%8,%9}, {%0,%1,%2,%3};\n"
        : "+f"(d0), "+f"(d1), "+f"(d2), "+f"(d3)
        : "r"(a0), "r"(a1), "r"(a2), "r"(a3), "r"(b0), "r"(b1));
}

// ---------------- tensor-core GEMM: C[M,N] = A[M,K] @ B[K,N] ----------------
// modes:
//  0: C[row][col] = acc                              (C, ldc)
//  1: C[row][col] = acc + aux[row][col]              (residual)
//  2: transposed: dT[b][col][t] = softplus(acc + aux[col])
//  3: transposed split: col<DI -> xinT[b][col][t], else zT[b][col-DI][t]
#define BM 128
#define BN 64
#define BK 32

__global__ __launch_bounds__(256) void mma_gemm(
    const float* __restrict__ A, const float* __restrict__ B,
    float* __restrict__ C, const float* __restrict__ aux,
    int K, int lda, int ldb, int ldc, int mode)
{
    __shared__ uint32_t As[BM][36];
    __shared__ uint32_t Bs[BK][68];

    const int tid = threadIdx.x;
    const int bm = blockIdx.y * BM;
    const int bn = blockIdx.x * BN;
    const int w  = tid >> 5;
    const int lane = tid & 31;
    const int g  = lane >> 2;
    const int tg = lane & 3;
    const int wm = (w & 3) * 32;
    const int wn = (w >> 2) * 32;

    const int ra = tid >> 3;
    const int ca = (tid & 7) * 4;
    const int rb = tid >> 4;
    const int cb = (tid & 15) * 4;

    float acc[2][4][4];
#pragma unroll
    for (int i = 0; i < 2; i++)
#pragma unroll
        for (int j = 0; j < 4; j++)
#pragma unroll
            for (int r = 0; r < 4; r++) acc[i][j][r] = 0.f;

    const int nk = K / BK;

    float4 pa[4], pb[2];
#pragma unroll
    for (int p = 0; p < 4; p++)
        pa[p] = *(const float4*)(A + (size_t)(bm + ra + p * 32) * lda + ca);
#pragma unroll
    for (int p = 0; p < 2; p++)
        pb[p] = *(const float4*)(B + (size_t)(rb + p * 16) * ldb + bn + cb);

    for (int kb = 0; kb < nk; kb++) {
#pragma unroll
        for (int p = 0; p < 4; p++) {
            uint4 v;
            v.x = f2tf32(pa[p].x); v.y = f2tf32(pa[p].y);
            v.z = f2tf32(pa[p].z); v.w = f2tf32(pa[p].w);
            *(uint4*)&As[ra + p * 32][ca] = v;
        }
#pragma unroll
        for (int p = 0; p < 2; p++) {
            uint4 v;
            v.x = f2tf32(pb[p].x); v.y = f2tf32(pb[p].y);
            v.z = f2tf32(pb[p].z); v.w = f2tf32(pb[p].w);
            *(uint4*)&Bs[rb + p * 16][cb] = v;
        }
        __syncthreads();

        if (kb + 1 < nk) {
            int k0 = (kb + 1) * BK;
#pragma unroll
            for (int p = 0; p < 4; p++)
                pa[p] = *(const float4*)(A + (size_t)(bm + ra + p * 32) * lda + k0 + ca);
#pragma unroll
            for (int p = 0; p < 2; p++)
                pb[p] = *(const float4*)(B + (size_t)(k0 + rb + p * 16) * ldb + bn + cb);
        }

#pragma unroll
        for (int ks = 0; ks < 4; ks++) {
            const int k8 = ks * 8;
            uint32_t af[2][4];
#pragma unroll
            for (int mt = 0; mt < 2; mt++) {
                int r0 = wm + mt * 16 + g;
                af[mt][0] = As[r0][k8 + tg];
                af[mt][1] = As[r0 + 8][k8 + tg];
                af[mt][2] = As[r0][k8 + tg + 4];
                af[mt][3] = As[r0 + 8][k8 + tg + 4];
            }
#pragma unroll
            for (int nt = 0; nt < 4; nt++) {
                int c0 = wn + nt * 8 + g;
                uint32_t b0 = Bs[k8 + tg][c0];
                uint32_t b1 = Bs[k8 + tg + 4][c0];
#pragma unroll
                for (int mt = 0; mt < 2; mt++)
                    mma_tf32(acc[mt][nt][0], acc[mt][nt][1],
                             acc[mt][nt][2], acc[mt][nt][3],
                             af[mt][0], af[mt][1], af[mt][2], af[mt][3],
                             b0, b1);
            }
        }
        __syncthreads();
    }

#pragma unroll
    for (int mt = 0; mt < 2; mt++) {
#pragma unroll
        for (int nt = 0; nt < 4; nt++) {
            int grow = bm + wm + mt * 16 + g;
            int gcol = bn + wn + nt * 8 + 2 * tg;
            float v0 = acc[mt][nt][0], v1 = acc[mt][nt][1];
            float v2 = acc[mt][nt][2], v3 = acc[mt][nt][3];
            if (mode <= 1) {
                if (mode == 1) {
                    float2 r0 = *(const float2*)(aux + (size_t)grow * ldc + gcol);
                    float2 r1 = *(const float2*)(aux + (size_t)(grow + 8) * ldc + gcol);
                    v0 += r0.x; v1 += r0.y; v2 += r1.x; v3 += r1.y;
                }
                float2 o0 = {v0, v1}, o1 = {v2, v3};
                *(float2*)(C + (size_t)grow * ldc + gcol) = o0;
                *(float2*)(C + (size_t)(grow + 8) * ldc + gcol) = o1;
            } else {
                int b = grow >> 10;
                int t = grow & (LSEQ - 1);
                if (mode == 2) {
                    float b0 = aux[gcol], b1 = aux[gcol + 1];
                    v0 += b0; v1 += b1; v2 += b0; v3 += b1;
                    v0 = (v0 > 20.f) ? v0 : log1pf(__expf(v0));
                    v1 = (v1 > 20.f) ? v1 : log1pf(__expf(v1));
                    v2 = (v2 > 20.f) ? v2 : log1pf(__expf(v2));
                    v3 = (v3 > 20.f) ? v3 : log1pf(__expf(v3));
                    float* dst = C + ((size_t)b * DI) * LSEQ;
                    dst[(size_t)gcol * LSEQ + t]           = v0;
                    dst[(size_t)(gcol + 1) * LSEQ + t]     = v1;
                    dst[(size_t)gcol * LSEQ + t + 8]       = v2;
                    dst[(size_t)(gcol + 1) * LSEQ + t + 8] = v3;
                } else { // mode 3: split-transpose (xin | z)
                    float* dst;
                    int c;
                    if (gcol < DI) { dst = g_xinT; c = gcol; }
                    else           { dst = g_zT;   c = gcol - DI; }
                    float* base = dst + ((size_t)b * DI) * LSEQ;
                    base[(size_t)c * LSEQ + t]           = v0;
                    base[(size_t)(c + 1) * LSEQ + t]     = v1;
                    base[(size_t)c * LSEQ + t + 8]       = v2;
                    base[(size_t)(c + 1) * LSEQ + t + 8] = v3;
                }
            }
        }
    }
}

// ---------------- depthwise causal conv (k=4) + bias + silu, channel-major --
// block: (b, 32 channels, 64 timesteps). Writes xsT (channel-major) and
// xs (row-major, via smem transpose).
__global__ __launch_bounds__(256) void conv2_k(
    const float* __restrict__ cw, const float* __restrict__ cb)
{
    __shared__ float tin[32][68];    // 3-halo + 64 t + pad
    __shared__ float tout[32][65];   // pad 65 -> conflict-free transpose
    const int b  = blockIdx.z;
    const int d0 = blockIdx.y * 32;
    const int t0 = blockIdx.x * 64;
    const int tid = threadIdx.x;

    for (int i = tid; i < 32 * 67; i += 256) {
        int dd = i / 67, j = i % 67;
        int t = t0 - 3 + j;
        float v = 0.f;
        if (t >= 0) v = g_xinT[((size_t)(b * DI + d0 + dd)) * LSEQ + t];
        tin[dd][j] = v;
    }
    __syncthreads();

    const int dd = tid >> 3;
    const int tq = tid & 7;
    const float* wp = cw + (d0 + dd) * 4;
    float w0 = wp[0], w1 = wp[1], w2 = wp[2], w3 = wp[3];
    float bias = cb[d0 + dd];

    float res[8];
#pragma unroll
    for (int half = 0; half < 2; half++) {
#pragma unroll
        for (int i = 0; i < 4; i++) {
            int j = half * 32 + tq * 4 + i;   // output t-index within tile
            float acc = bias;
            acc = fmaf(w0, tin[dd][j],     acc);
            acc = fmaf(w1, tin[dd][j + 1], acc);
            acc = fmaf(w2, tin[dd][j + 2], acc);
            acc = fmaf(w3, tin[dd][j + 3], acc);
            acc = acc / (1.f + __expf(-acc));
            res[half * 4 + i] = acc;
            tout[dd][j] = acc;
        }
    }
    // xsT: contiguous float4 stores
    float* dstT = g_xsT + ((size_t)(b * DI + d0 + dd)) * LSEQ + t0;
    *(float4*)(dstT + tq * 4)      = make_float4(res[0], res[1], res[2], res[3]);
    *(float4*)(dstT + 32 + tq * 4) = make_float4(res[4], res[5], res[6], res[7]);
    __syncthreads();

    // xs row-major: coalesced along d
    const int dw = tid & 31;
    const int tw = tid >> 5;   // 0..7
#pragma unroll
    for (int it = 0; it < 8; it++) {
        int tl = it * 8 + tw;
        g_xs[((size_t)(b * LSEQ + t0 + tl)) * DI + d0 + dw] = tout[dw][tl];
    }
}

// ---------------- selective scan (gate fused), channel-major streaming -----
// 16 lanes per channel (one state each), 2 channels per warp.
__global__ __launch_bounds__(256) void scan_k(
    const float* __restrict__ A_log, const float* __restrict__ Dsk)
{
    int tid = blockIdx.x * 256 + threadIdx.x;
    int w = tid >> 5;
    int lane = tid & 31;
    int half = lane >> 4;
    int n = lane & 15;
    int b = w / (DI / 2);
    int dp = w % (DI / 2);
    int d = dp * 2 + half;

    float a = -expf(A_log[d * DS + n]);
    float Dv = Dsk[d];

    const float* dT = g_dT   + ((size_t)(b * DI + d)) * LSEQ;
    const float* xT = g_xsT  + ((size_t)(b * DI + d)) * LSEQ;
    const float* zT = g_zT   + ((size_t)(b * DI + d)) * LSEQ;
    const float* bc = g_dbc  + ((size_t)b * LSEQ) * 64;
    float*       yp = g_y    + ((size_t)b * LSEQ) * DI + d;

    float h = 0.f;
    for (int t4 = 0; t4 < LSEQ; t4 += 4) {
        float4 d4 = *(const float4*)(dT + t4);
        float4 x4 = *(const float4*)(xT + t4);
        float4 z4 = *(const float4*)(zT + t4);
        // prefetch all B/C for the group (independent loads -> MLP)
        float Bn[4], Cn[4];
#pragma unroll
        for (int j = 0; j < 4; j++) {
            const float* bcp = bc + (size_t)(t4 + j) * 64;
            Bn[j] = __ldg(bcp + 32 + n);
            Cn[j] = __ldg(bcp + 48 + n);
        }
        float dv[4] = {d4.x, d4.y, d4.z, d4.w};
        float xv[4] = {x4.x, x4.y, x4.z, x4.w};
        float zv[4] = {z4.x, z4.y, z4.z, z4.w};
#pragma unroll
        for (int j = 0; j < 4; j++) {
            float delta = dv[j];
            float dA = __expf(delta * a);
            h = fmaf(dA, h, (delta * xv[j]) * Bn[j]);
            float p = h * Cn[j];
            p += __shfl_xor_sync(0xffffffffu, p, 8);
            p += __shfl_xor_sync(0xffffffffu, p, 4);
            p += __shfl_xor_sync(0xffffffffu, p, 2);
            p += __shfl_xor_sync(0xffffffffu, p, 1);
            if (n == 0) {
                float z = zv[j];
                float y = fmaf(xv[j], Dv, p);
                yp[(size_t)(t4 + j) * DI] = y * (z / (1.f + __expf(-z)));
            }
        }
    }
}

// ---------------- layernorm over DM=512 ----------------
__global__ __launch_bounds__(256) void ln_k(
    const float* __restrict__ g, const float* __restrict__ bb,
    float* __restrict__ out)
{
    __shared__ float red[256];
    int row = blockIdx.x;
    const float* r = g_res + (size_t)row * DM;
    int tid = threadIdx.x;
    float v0 = r[tid], v1 = r[tid + 256];
    red[tid] = v0 + v1;
    __syncthreads();
    for (int o = 128; o > 0; o >>= 1) {
        if (tid < o) red[tid] += red[tid + o];
        __syncthreads();
    }
    float mean = red[0] * (1.f / 512.f);
    __syncthreads();
    float d0 = v0 - mean, d1 = v1 - mean;
    red[tid] = d0 * d0 + d1 * d1;
    __syncthreads();
    for (int o = 128; o > 0; o >>= 1) {
        if (tid < o) red[tid] += red[tid + o];
        __syncthreads();
    }
    float rs = rsqrtf(red[0] * (1.f / 512.f) + LN_EPS);
    out[(size_t)row * DM + tid]       = d0 * rs * g[tid]       + bb[tid];
    out[(size_t)row * DM + tid + 256] = d1 * rs * g[tid + 256] + bb[tid + 256];
}

// ---------------- host orchestration ----------------
extern "C" void kernel_launch(void* const* d_in, const int* in_sizes, int n_in,
                              void* d_out, int out_size)
{
    const float* x     = (const float*)d_in[0];
    const float* Wi    = (const float*)d_in[1];
    const float* cw    = (const float*)d_in[2];
    const float* cb    = (const float*)d_in[3];
    const float* Wx    = (const float*)d_in[4];
    const float* Wdt   = (const float*)d_in[5];
    const float* bdt   = (const float*)d_in[6];
    const float* A_log = (const float*)d_in[7];
    const float* Dsk   = (const float*)d_in[8];
    const float* Wo    = (const float*)d_in[9];
    const float* lng   = (const float*)d_in[10];
    const float* lnb   = (const float*)d_in[11];
    float* out = (float*)d_out;

    float *p_xs, *p_dbc, *p_dT, *p_y, *p_res;
    cudaGetSymbolAddress((void**)&p_xs,  g_xs);
    cudaGetSymbolAddress((void**)&p_dbc, g_dbc);
    cudaGetSymbolAddress((void**)&p_dT,  g_dT);
    cudaGetSymbolAddress((void**)&p_y,   g_y);
    cudaGetSymbolAddress((void**)&p_res, g_res);

    for (int l = 0; l < 2; l++) {
        const float* hin = (l == 0) ? x : out;

        // GEMM1: xz = hin @ Wi[l], written split-transposed -> g_xinT, g_zT
        mma_gemm<<<dim3(2 * DI / BN, NROWS / BM), 256>>>(
            hin, Wi + (size_t)l * DM * 2 * DI, nullptr, nullptr,
            DM, DM, 2 * DI, 0, 3);

        // conv + silu: xinT -> xsT (channel-major) + xs (row-major)
        conv2_k<<<dim3(LSEQ / 64, DI / 32, BATCH), 256>>>(
            cw + (size_t)l * DI * 4, cb + (size_t)l * DI);

        // GEMM2: dbc = xs @ Wx[l]  [4096,1024]x[1024,64] (row-major out)
        mma_gemm<<<dim3(64 / BN, NROWS / BM), 256>>>(
            p_xs, Wx + (size_t)l * DI * 64, p_dbc, nullptr,
            DI, DI, 64, 64, 0);

        // GEMM3: deltaT = softplus(dt @ Wdt[l] + bdt), transposed out
        mma_gemm<<<dim3(DI / BN, NROWS / BM), 256>>>(
            p_dbc, Wdt + (size_t)l * DTR * DI, p_dT, bdt + (size_t)l * DI,
            DTR, 64, DI, 0, 2);

        // selective scan (+D skip, +gate fused) -> g_y row-major
        scan_k<<<(BATCH * (DI / 2) * 32) / 256, 256>>>(
            A_log + (size_t)l * DI * DS, Dsk + (size_t)l * DI);

        // GEMM4: res = y @ Wo[l] + hin
        mma_gemm<<<dim3(DM / BN, NROWS / BM), 256>>>(
            p_y, Wo + (size_t)l * DI * DM, p_res, hin,
            DI, DI, DM, DM, 1);

        // layernorm -> out
        ln_k<<<NROWS, 256>>>(lng + (size_t)l * DM, lnb + (size_t)l * DM, out);
    }
}

// round 4
// speedup vs baseline: 2.4248x; 1.0966x over previous
#include <cuda_runtime.h>
#include <math.h>
#include <stdint.h>

// ---------------- problem constants ----------------
#define BATCH   4
#define LSEQ    1024
#define DM      512
#define DI      1024      // d_inner
#define DS      16        // d_state
#define DTR     32        // dt_rank
#define NROWS   (BATCH*LSEQ)   // 4096
#define LN_EPS  1e-5f

// ---------------- scratch (device globals; no allocs allowed) ----------------
__device__ float g_xinT[BATCH * DI * LSEQ];   // in_proj x-half, [b][d][t]
__device__ float g_zT  [BATCH * DI * LSEQ];   // in_proj z-half, [b][d][t]
__device__ float g_xsT [BATCH * DI * LSEQ];   // conv+silu, [b][d][t] (scan)
__device__ float g_xs  [NROWS * DI];          // conv+silu, [row][d]  (GEMM2)
__device__ float g_dbc [NROWS * 64];          // x_proj out [row][64] (dt|B|C)
__device__ float g_dT  [BATCH * DI * LSEQ];   // delta, [b][d][t]
__device__ float g_y   [NROWS * DI];          // scan out (gated), [row][d]
__device__ float g_res [NROWS * DM];          // out_proj + residual (LN input)

// ---------------- tf32 helpers ----------------
__device__ __forceinline__ uint32_t f2tf32(float x) {
    uint32_t r;
    asm("cvt.rna.tf32.f32 %0, %1;" : "=r"(r) : "f"(x));
    return r;
}

__device__ __forceinline__ void mma_tf32(
    float& d0, float& d1, float& d2, float& d3,
    uint32_t a0, uint32_t a1, uint32_t a2, uint32_t a3,
    uint32_t b0, uint32_t b1)
{
    asm volatile(
        "mma.sync.aligned.m16n8k8.row.col.f32.tf32.tf32.f32 "
        "{%0,%1,%2,%3}, {%4,%5,%6,%7}, {%8,%9}, {%0,%1,%2,%3};\n"
        : "+f"(d0), "+f"(d1), "+f"(d2), "+f"(d3)
        : "r"(a0), "r"(a1), "r"(a2), "r"(a3), "r"(b0), "r"(b1));
}

// ---------------- tensor-core GEMM: C[M,N] = A[M,K] @ B[K,N] ----------------
// modes:
//  0: C[row][col] = acc
//  1: C[row][col] = acc + aux[row][col]              (residual)
//  2: transposed: dT[b][col][t] = softplus(acc + aux[col])
//  3: transposed split: col<DI -> xinT[b][col][t], else zT[b][col-DI][t]
#define BM 128
#define BN 64
#define BK 32

__global__ __launch_bounds__(256) void mma_gemm(
    const float* __restrict__ A, const float* __restrict__ B,
    float* __restrict__ C, const float* __restrict__ aux,
    int K, int lda, int ldb, int ldc, int mode)
{
    __shared__ uint32_t As[BM][36];
    __shared__ uint32_t Bs[BK][68];

    const int tid = threadIdx.x;
    const int bm = blockIdx.y * BM;
    const int bn = blockIdx.x * BN;
    const int w  = tid >> 5;
    const int lane = tid & 31;
    const int g  = lane >> 2;
    const int tg = lane & 3;
    const int wm = (w & 3) * 32;
    const int wn = (w >> 2) * 32;

    const int ra = tid >> 3;
    const int ca = (tid & 7) * 4;
    const int rb = tid >> 4;
    const int cb = (tid & 15) * 4;

    float acc[2][4][4];
#pragma unroll
    for (int i = 0; i < 2; i++)
#pragma unroll
        for (int j = 0; j < 4; j++)
#pragma unroll
            for (int r = 0; r < 4; r++) acc[i][j][r] = 0.f;

    const int nk = K / BK;

    float4 pa[4], pb[2];
#pragma unroll
    for (int p = 0; p < 4; p++)
        pa[p] = *(const float4*)(A + (size_t)(bm + ra + p * 32) * lda + ca);
#pragma unroll
    for (int p = 0; p < 2; p++)
        pb[p] = *(const float4*)(B + (size_t)(rb + p * 16) * ldb + bn + cb);

    for (int kb = 0; kb < nk; kb++) {
#pragma unroll
        for (int p = 0; p < 4; p++) {
            uint4 v;
            v.x = f2tf32(pa[p].x); v.y = f2tf32(pa[p].y);
            v.z = f2tf32(pa[p].z); v.w = f2tf32(pa[p].w);
            *(uint4*)&As[ra + p * 32][ca] = v;
        }
#pragma unroll
        for (int p = 0; p < 2; p++) {
            uint4 v;
            v.x = f2tf32(pb[p].x); v.y = f2tf32(pb[p].y);
            v.z = f2tf32(pb[p].z); v.w = f2tf32(pb[p].w);
            *(uint4*)&Bs[rb + p * 16][cb] = v;
        }
        __syncthreads();

        if (kb + 1 < nk) {
            int k0 = (kb + 1) * BK;
#pragma unroll
            for (int p = 0; p < 4; p++)
                pa[p] = *(const float4*)(A + (size_t)(bm + ra + p * 32) * lda + k0 + ca);
#pragma unroll
            for (int p = 0; p < 2; p++)
                pb[p] = *(const float4*)(B + (size_t)(k0 + rb + p * 16) * ldb + bn + cb);
        }

#pragma unroll
        for (int ks = 0; ks < 4; ks++) {
            const int k8 = ks * 8;
            uint32_t af[2][4];
#pragma unroll
            for (int mt = 0; mt < 2; mt++) {
                int r0 = wm + mt * 16 + g;
                af[mt][0] = As[r0][k8 + tg];
                af[mt][1] = As[r0 + 8][k8 + tg];
                af[mt][2] = As[r0][k8 + tg + 4];
                af[mt][3] = As[r0 + 8][k8 + tg + 4];
            }
#pragma unroll
            for (int nt = 0; nt < 4; nt++) {
                int c0 = wn + nt * 8 + g;
                uint32_t b0 = Bs[k8 + tg][c0];
                uint32_t b1 = Bs[k8 + tg + 4][c0];
#pragma unroll
                for (int mt = 0; mt < 2; mt++)
                    mma_tf32(acc[mt][nt][0], acc[mt][nt][1],
                             acc[mt][nt][2], acc[mt][nt][3],
                             af[mt][0], af[mt][1], af[mt][2], af[mt][3],
                             b0, b1);
            }
        }
        __syncthreads();
    }

#pragma unroll
    for (int mt = 0; mt < 2; mt++) {
#pragma unroll
        for (int nt = 0; nt < 4; nt++) {
            int grow = bm + wm + mt * 16 + g;
            int gcol = bn + wn + nt * 8 + 2 * tg;
            float v0 = acc[mt][nt][0], v1 = acc[mt][nt][1];
            float v2 = acc[mt][nt][2], v3 = acc[mt][nt][3];
            if (mode <= 1) {
                if (mode == 1) {
                    float2 r0 = *(const float2*)(aux + (size_t)grow * ldc + gcol);
                    float2 r1 = *(const float2*)(aux + (size_t)(grow + 8) * ldc + gcol);
                    v0 += r0.x; v1 += r0.y; v2 += r1.x; v3 += r1.y;
                }
                float2 o0 = {v0, v1}, o1 = {v2, v3};
                *(float2*)(C + (size_t)grow * ldc + gcol) = o0;
                *(float2*)(C + (size_t)(grow + 8) * ldc + gcol) = o1;
            } else {
                int b = grow >> 10;
                int t = grow & (LSEQ - 1);
                if (mode == 2) {
                    float b0 = aux[gcol], b1 = aux[gcol + 1];
                    v0 += b0; v1 += b1; v2 += b0; v3 += b1;
                    v0 = (v0 > 20.f) ? v0 : __logf(1.f + __expf(v0));
                    v1 = (v1 > 20.f) ? v1 : __logf(1.f + __expf(v1));
                    v2 = (v2 > 20.f) ? v2 : __logf(1.f + __expf(v2));
                    v3 = (v3 > 20.f) ? v3 : __logf(1.f + __expf(v3));
                    float* dst = C + ((size_t)b * DI) * LSEQ;
                    dst[(size_t)gcol * LSEQ + t]           = v0;
                    dst[(size_t)(gcol + 1) * LSEQ + t]     = v1;
                    dst[(size_t)gcol * LSEQ + t + 8]       = v2;
                    dst[(size_t)(gcol + 1) * LSEQ + t + 8] = v3;
                } else { // mode 3: split-transpose (xin | z)
                    float* dst;
                    int c;
                    if (gcol < DI) { dst = g_xinT; c = gcol; }
                    else           { dst = g_zT;   c = gcol - DI; }
                    float* base = dst + ((size_t)b * DI) * LSEQ;
                    base[(size_t)c * LSEQ + t]           = v0;
                    base[(size_t)(c + 1) * LSEQ + t]     = v1;
                    base[(size_t)c * LSEQ + t + 8]       = v2;
                    base[(size_t)(c + 1) * LSEQ + t + 8] = v3;
                }
            }
        }
    }
}

// ---------------- depthwise causal conv (k=4) + bias + silu, channel-major --
__global__ __launch_bounds__(256) void conv2_k(
    const float* __restrict__ cw, const float* __restrict__ cb)
{
    __shared__ float tin[32][68];
    __shared__ float tout[32][65];
    const int b  = blockIdx.z;
    const int d0 = blockIdx.y * 32;
    const int t0 = blockIdx.x * 64;
    const int tid = threadIdx.x;

    for (int i = tid; i < 32 * 67; i += 256) {
        int dd = i / 67, j = i % 67;
        int t = t0 - 3 + j;
        float v = 0.f;
        if (t >= 0) v = g_xinT[((size_t)(b * DI + d0 + dd)) * LSEQ + t];
        tin[dd][j] = v;
    }
    __syncthreads();

    const int dd = tid >> 3;
    const int tq = tid & 7;
    const float* wp = cw + (d0 + dd) * 4;
    float w0 = wp[0], w1 = wp[1], w2 = wp[2], w3 = wp[3];
    float bias = cb[d0 + dd];

    float res[8];
#pragma unroll
    for (int half = 0; half < 2; half++) {
#pragma unroll
        for (int i = 0; i < 4; i++) {
            int j = half * 32 + tq * 4 + i;
            float acc = bias;
            acc = fmaf(w0, tin[dd][j],     acc);
            acc = fmaf(w1, tin[dd][j + 1], acc);
            acc = fmaf(w2, tin[dd][j + 2], acc);
            acc = fmaf(w3, tin[dd][j + 3], acc);
            acc = acc / (1.f + __expf(-acc));
            res[half * 4 + i] = acc;
            tout[dd][j] = acc;
        }
    }
    float* dstT = g_xsT + ((size_t)(b * DI + d0 + dd)) * LSEQ + t0;
    *(float4*)(dstT + tq * 4)      = make_float4(res[0], res[1], res[2], res[3]);
    *(float4*)(dstT + 32 + tq * 4) = make_float4(res[4], res[5], res[6], res[7]);
    __syncthreads();

    const int dw = tid & 31;
    const int tw = tid >> 5;
#pragma unroll
    for (int it = 0; it < 8; it++) {
        int tl = it * 8 + tw;
        g_xs[((size_t)(b * LSEQ + t0 + tl)) * DI + d0 + dw] = tout[dw][tl];
    }
}

// ---------------- selective scan (gate fused), pipelined, batched shfl -----
// 16 lanes per channel (one state each), 2 channels per warp.
// 8-step groups; next group's streams prefetched before current compute.
__global__ __launch_bounds__(256) void scan_k(
    const float* __restrict__ A_log, const float* __restrict__ Dsk)
{
    int tid = blockIdx.x * 256 + threadIdx.x;
    int w = tid >> 5;
    int lane = tid & 31;
    int half = lane >> 4;
    int n = lane & 15;
    int b = w / (DI / 2);
    int dp = w % (DI / 2);
    int d = dp * 2 + half;

    const float a  = -expf(A_log[d * DS + n]);
    const float Dv = Dsk[d];

    const float* dT = g_dT  + ((size_t)(b * DI + d)) * LSEQ;
    const float* xT = g_xsT + ((size_t)(b * DI + d)) * LSEQ;
    const float* zT = g_zT  + ((size_t)(b * DI + d)) * LSEQ;
    const float* bc = g_dbc + ((size_t)b * LSEQ) * 64;
    float*       yp = g_y   + ((size_t)b * LSEQ) * DI + d;

    // prefetch registers for the three streams (two float4 each = 8 steps)
    float4 nd0 = *(const float4*)(dT);
    float4 nd1 = *(const float4*)(dT + 4);
    float4 nx0 = *(const float4*)(xT);
    float4 nx1 = *(const float4*)(xT + 4);
    float4 nz0 = *(const float4*)(zT);
    float4 nz1 = *(const float4*)(zT + 4);

    float h = 0.f;
    for (int t8 = 0; t8 < LSEQ; t8 += 8) {
        // take prefetched values
        float dv[8] = {nd0.x, nd0.y, nd0.z, nd0.w, nd1.x, nd1.y, nd1.z, nd1.w};
        float xv[8] = {nx0.x, nx0.y, nx0.z, nx0.w, nx1.x, nx1.y, nx1.z, nx1.w};
        float zv[8] = {nz0.x, nz0.y, nz0.z, nz0.w, nz1.x, nz1.y, nz1.z, nz1.w};

        // prefetch next group (hidden behind compute below)
        if (t8 + 8 < LSEQ) {
            nd0 = *(const float4*)(dT + t8 + 8);
            nd1 = *(const float4*)(dT + t8 + 12);
            nx0 = *(const float4*)(xT + t8 + 8);
            nx1 = *(const float4*)(xT + t8 + 12);
            nz0 = *(const float4*)(zT + t8 + 8);
            nz1 = *(const float4*)(zT + t8 + 12);
        }

        // B/C loads (L1-resident: shared by all 512 channel-warps of batch b)
        float Bn[8], Cn[8];
#pragma unroll
        for (int j = 0; j < 8; j++) {
            const float* bcp = bc + (size_t)(t8 + j) * 64;
            Bn[j] = __ldg(bcp + 32 + n);
            Cn[j] = __ldg(bcp + 48 + n);
        }

        // serial h-chain (the only true dependency), collect p[j]
        float p[8];
#pragma unroll
        for (int j = 0; j < 8; j++) {
            float delta = dv[j];
            float dA = __expf(delta * a);
            h = fmaf(dA, h, (delta * xv[j]) * Bn[j]);
            p[j] = h * Cn[j];
        }

        // 8 independent shfl trees, interleaved (chain depth 4, not 32)
#pragma unroll
        for (int off = 8; off >= 1; off >>= 1) {
#pragma unroll
            for (int j = 0; j < 8; j++)
                p[j] += __shfl_xor_sync(0xffffffffu, p[j], off);
        }

        // gate + store (lanes n==0 of each half-warp)
        if (n == 0) {
#pragma unroll
            for (int j = 0; j < 8; j++) {
                float z = zv[j];
                float y = fmaf(xv[j], Dv, p[j]);
                yp[(size_t)(t8 + j) * DI] = y * (z / (1.f + __expf(-z)));
            }
        }
    }
}

// ---------------- layernorm over DM=512 ----------------
__global__ __launch_bounds__(256) void ln_k(
    const float* __restrict__ g, const float* __restrict__ bb,
    float* __restrict__ out)
{
    __shared__ float red[256];
    int row = blockIdx.x;
    const float* r = g_res + (size_t)row * DM;
    int tid = threadIdx.x;
    float v0 = r[tid], v1 = r[tid + 256];
    red[tid] = v0 + v1;
    __syncthreads();
    for (int o = 128; o > 0; o >>= 1) {
        if (tid < o) red[tid] += red[tid + o];
        __syncthreads();
    }
    float mean = red[0] * (1.f / 512.f);
    __syncthreads();
    float d0 = v0 - mean, d1 = v1 - mean;
    red[tid] = d0 * d0 + d1 * d1;
    __syncthreads();
    for (int o = 128; o > 0; o >>= 1) {
        if (tid < o) red[tid] += red[tid + o];
        __syncthreads();
    }
    float rs = rsqrtf(red[0] * (1.f / 512.f) + LN_EPS);
    out[(size_t)row * DM + tid]       = d0 * rs * g[tid]       + bb[tid];
    out[(size_t)row * DM + tid + 256] = d1 * rs * g[tid + 256] + bb[tid + 256];
}

// ---------------- host orchestration ----------------
extern "C" void kernel_launch(void* const* d_in, const int* in_sizes, int n_in,
                              void* d_out, int out_size)
{
    const float* x     = (const float*)d_in[0];
    const float* Wi    = (const float*)d_in[1];
    const float* cw    = (const float*)d_in[2];
    const float* cb    = (const float*)d_in[3];
    const float* Wx    = (const float*)d_in[4];
    const float* Wdt   = (const float*)d_in[5];
    const float* bdt   = (const float*)d_in[6];
    const float* A_log = (const float*)d_in[7];
    const float* Dsk   = (const float*)d_in[8];
    const float* Wo    = (const float*)d_in[9];
    const float* lng   = (const float*)d_in[10];
    const float* lnb   = (const float*)d_in[11];
    float* out = (float*)d_out;

    float *p_xs, *p_dbc, *p_dT, *p_y, *p_res;
    cudaGetSymbolAddress((void**)&p_xs,  g_xs);
    cudaGetSymbolAddress((void**)&p_dbc, g_dbc);
    cudaGetSymbolAddress((void**)&p_dT,  g_dT);
    cudaGetSymbolAddress((void**)&p_y,   g_y);
    cudaGetSymbolAddress((void**)&p_res, g_res);

    for (int l = 0; l < 2; l++) {
        const float* hin = (l == 0) ? x : out;

        // GEMM1: xz = hin @ Wi[l], written split-transposed -> g_xinT, g_zT
        mma_gemm<<<dim3(2 * DI / BN, NROWS / BM), 256>>>(
            hin, Wi + (size_t)l * DM * 2 * DI, nullptr, nullptr,
            DM, DM, 2 * DI, 0, 3);

        // conv + silu: xinT -> xsT (channel-major) + xs (row-major)
        conv2_k<<<dim3(LSEQ / 64, DI / 32, BATCH), 256>>>(
            cw + (size_t)l * DI * 4, cb + (size_t)l * DI);

        // GEMM2: dbc = xs @ Wx[l]
        mma_gemm<<<dim3(64 / BN, NROWS / BM), 256>>>(
            p_xs, Wx + (size_t)l * DI * 64, p_dbc, nullptr,
            DI, DI, 64, 64, 0);

        // GEMM3: deltaT = softplus(dt @ Wdt[l] + bdt), transposed out
        mma_gemm<<<dim3(DI / BN, NROWS / BM), 256>>>(
            p_dbc, Wdt + (size_t)l * DTR * DI, p_dT, bdt + (size_t)l * DI,
            DTR, 64, DI, 0, 2);

        // selective scan (+D skip, +gate fused) -> g_y row-major
        scan_k<<<(BATCH * (DI / 2) * 32) / 256, 256>>>(
            A_log + (size_t)l * DI * DS, Dsk + (size_t)l * DI);

        // GEMM4: res = y @ Wo[l] + hin
        mma_gemm<<<dim3(DM / BN, NROWS / BM), 256>>>(
            p_y, Wo + (size_t)l * DI * DM, p_res, hin,
            DI, DI, DM, DM, 1);

        // layernorm -> out
        ln_k<<<NROWS, 256>>>(lng + (size_t)l * DM, lnb + (size_t)l * DM, out);
    }
}